// round 17
// baseline (speedup 1.0000x reference)
#include <cuda_runtime.h>

// SSIM (skimage, win=7, data_range=2) of two 4096x4096 f32 -> scalar mean.
// 4 output cols/thread; vertical 7-row ring for quantities T,Q,R lives in
// SMEM (conflict-free [slot][tid] float4) to cut regs ~200 -> <=128, giving
// 4 CTAs/SM = 16 warps/SM for latency hiding. O-ring stays in registers.

#define IMW  4096
#define OWD  4090
#define OHT  4090
#define TPB  128
#define GX   8            // 8 * 128 thr * 4 cols = 4096 columns
#define RH   56           // output rows per strip (multiple of 7)
#define NSTR 74           // 74*56 = 4144 >= 4090
#define NBLK (GX * NSTR)  // 592 = 148 * 4 -> one balanced wave at 4 CTA/SM

__device__ double   g_sum;   // zero-init; reset by last block each run
__device__ unsigned g_cnt;

__global__ __launch_bounds__(TPB, 4) void ssim_main(
    const float* __restrict__ O, const float* __restrict__ T,
    float* __restrict__ out)
{
    // SMEM rings: [slot][tid], float4 per thread -> LDS/STS.128 conflict-free.
    __shared__ float4 rgT[7][TPB];
    __shared__ float4 rgQ[7][TPB];
    __shared__ float4 rgR[7][TPB];
    __shared__ float  ws[TPB / 32];

    const int tid  = threadIdx.x;
    const int gid  = blockIdx.x * TPB + tid;   // 0..1023
    const int ocol = gid * 4;
    int  c   = ocol;
    bool ld3 = (c + 11 < IMW);
    if (c >= OWD) { c = 4084; ld3 = true; }    // fully-masked thread: safe loads

    const int r0       = blockIdx.y * RH;
    const int rows_out = min(RH, OHT - r0);

    const float4* __restrict__ O4 = (const float4*)O;
    const float4* __restrict__ T4 = (const float4*)T;
    int p = r0 * (IMW / 4) + (c >> 2);

    // Scaled constants: raw 7x7 sums S = 49*mean; 1/49^2 cancels in the ratio.
    const float C1p = 0.9604f;                 // C1 * 49^2
    const float C2p = 8.6436f;                 // C2 * 49^2
    const float a2s = 98.0f * (49.0f / 48.0f); // 2*COV*49
    const float a2p = 2.0f  * (49.0f / 48.0f); // 2*COV
    const float b2s = 49.0f * (49.0f / 48.0f); // COV*49
    const float b2q = (49.0f / 48.0f);         // COV

    // O-quantity ring stays in registers (compile-time indexed).
    float rO0[7], rO1[7], rO2[7], rO3[7];
    // Vertical running 7-row sums.
    float vO0=0.f,vO1=0.f,vO2=0.f,vO3=0.f, vT0=0.f,vT1=0.f,vT2=0.f,vT3=0.f;
    float vQ0=0.f,vQ1=0.f,vQ2=0.f,vQ3=0.f, vR0=0.f,vR1=0.f,vR2=0.f,vR3=0.f;
    float accA = 0.f, accB = 0.f;

// Load 12 px/row/image, horizontal 7-sums for 4 cols, quantities {o,t,o^2+t^2,o*t}.
#define ROWH() \
    float hO0,hO1,hO2,hO3, hT0,hT1,hT2,hT3, hQ0,hQ1,hQ2,hQ3, hR0,hR1,hR2,hR3; \
    { \
        float4 A0 = O4[p], A1 = O4[p+1], B0 = T4[p], B1 = T4[p+1]; \
        float4 A2 = make_float4(0.f,0.f,0.f,0.f), B2 = A2; \
        if (ld3) { A2 = O4[p+2]; B2 = T4[p+2]; } \
        p += IMW / 4; \
        float o0=A0.x,o1=A0.y,o2=A0.z,o3=A0.w,o4=A1.x,o5=A1.y,o6=A1.z,o7=A1.w,o8=A2.x,o9=A2.y; \
        float t0=B0.x,t1=B0.y,t2=B0.z,t3=B0.w,t4=B1.x,t5=B1.y,t6=B1.z,t7=B1.w,t8=B2.x,t9=B2.y; \
        hO0 = ((o0+o1)+(o2+o3))+((o4+o5)+o6); \
        hO1 = (hO0-o0)+o7; hO2 = (hO1-o1)+o8; hO3 = (hO2-o2)+o9; \
        hT0 = ((t0+t1)+(t2+t3))+((t4+t5)+t6); \
        hT1 = (hT0-t0)+t7; hT2 = (hT1-t1)+t8; hT3 = (hT2-t2)+t9; \
        float q0=fmaf(o0,o0,t0*t0), q1=fmaf(o1,o1,t1*t1), q2=fmaf(o2,o2,t2*t2); \
        float q3=fmaf(o3,o3,t3*t3), q4=fmaf(o4,o4,t4*t4), q5=fmaf(o5,o5,t5*t5); \
        float q6=fmaf(o6,o6,t6*t6), q7=fmaf(o7,o7,t7*t7), q8=fmaf(o8,o8,t8*t8); \
        float q9=fmaf(o9,o9,t9*t9); \
        hQ0 = ((q0+q1)+(q2+q3))+((q4+q5)+q6); \
        hQ1 = (hQ0-q0)+q7; hQ2 = (hQ1-q1)+q8; hQ3 = (hQ2-q2)+q9; \
        float w0=o0*t0, w1=o1*t1, w2=o2*t2, w3=o3*t3, w4=o4*t4; \
        float w5=o5*t5, w6=o6*t6, w7=o7*t7, w8=o8*t8, w9=o9*t9; \
        hR0 = ((w0+w1)+(w2+w3))+((w4+w5)+w6); \
        hR1 = (hR0-w0)+w7; hR2 = (hR1-w1)+w8; hR3 = (hR2-w2)+w9; \
    }

// Two SSIM values with one divide: S0+S1 = (N0*D1 + N1*D0) / (D0*D1).
#define SSIMPAIR(SxA,SyA,SqA,SrA, SxB,SyB,SqB,SrB, ACC) do { \
        float PA  = (SxA) * (SyA); \
        float QA  = fmaf((SxA),(SxA), (SyA)*(SyA)); \
        float A1A = fmaf(2.f, PA, C1p); \
        float B1A = QA + C1p; \
        float A2A = fmaf(a2s, (SrA), fmaf(-a2p, PA, C2p)); \
        float B2A = fmaf(b2s, (SqA), fmaf(-b2q, QA, C2p)); \
        float NA  = A1A * A2A, DA = B1A * B2A; \
        float PB  = (SxB) * (SyB); \
        float QB  = fmaf((SxB),(SxB), (SyB)*(SyB)); \
        float A1B = fmaf(2.f, PB, C1p); \
        float B1B = QB + C1p; \
        float A2B = fmaf(a2s, (SrB), fmaf(-a2p, PB, C2p)); \
        float B2B = fmaf(b2s, (SqB), fmaf(-b2q, QB, C2p)); \
        float NB  = A1B * A2B, DB = B1B * B2B; \
        ACC += __fdividef(fmaf(NA, DB, NB * DA), DA * DB); \
    } while (0)

#define ADDH() do { \
        vO0+=hO0; vO1+=hO1; vO2+=hO2; vO3+=hO3; \
        vT0+=hT0; vT1+=hT1; vT2+=hT2; vT3+=hT3; \
        vQ0+=hQ0; vQ1+=hQ1; vQ2+=hQ2; vQ3+=hQ3; \
        vR0+=hR0; vR1+=hR1; vR2+=hR2; vR3+=hR3; \
    } while (0)

#define STORE_RING(S) do { \
        rgT[S][tid] = make_float4(hT0,hT1,hT2,hT3); \
        rgQ[S][tid] = make_float4(hQ0,hQ1,hQ2,hQ3); \
        rgR[S][tid] = make_float4(hR0,hR1,hR2,hR3); \
        rO0[S]=hO0; rO1[S]=hO1; rO2[S]=hO2; rO3[S]=hO3; \
    } while (0)

#define PRIME(S) do { ROWH(); ADDH(); STORE_RING(S); } while (0)

    // Prime with input rows r0 .. r0+5 (ring slots 0..5). Slot 6 is written
    // by BODY(0) before BODY(6) reads it, so no zero-init needed.
    PRIME(0); PRIME(1); PRIME(2); PRIME(3); PRIME(4); PRIME(5);

// Output row (K = j%7): read leaving row early (latency), add new row's h,
// SSIM, drop oldest, store new into slot (K+6)%7.
#define BODY(K) do { \
        float4 oT = rgT[K][tid]; \
        float4 oQ = rgQ[K][tid]; \
        float4 oR = rgR[K][tid]; \
        ROWH(); ADDH(); \
        SSIMPAIR(vO0,vT0,vQ0,vR0, vO1,vT1,vQ1,vR1, accA); \
        SSIMPAIR(vO2,vT2,vQ2,vR2, vO3,vT3,vQ3,vR3, accB); \
        vT0-=oT.x; vT1-=oT.y; vT2-=oT.z; vT3-=oT.w; \
        vQ0-=oQ.x; vQ1-=oQ.y; vQ2-=oQ.z; vQ3-=oQ.w; \
        vR0-=oR.x; vR1-=oR.y; vR2-=oR.z; vR3-=oR.w; \
        vO0-=rO0[K]; vO1-=rO1[K]; vO2-=rO2[K]; vO3-=rO3[K]; \
        STORE_RING(((K)+6)%7); \
    } while (0)

    const int full = (rows_out / 7) * 7;
    int j = 0;
    while (j < full) {
        BODY(0); BODY(1); BODY(2); BODY(3); BODY(4); BODY(5); BODY(6);
        j += 7;
    }
    const int rem = rows_out - full;   // 0..6 (only last strip)
    if (rem > 0) BODY(0);
    if (rem > 1) BODY(1);
    if (rem > 2) BODY(2);
    if (rem > 3) BODY(3);
    if (rem > 4) BODY(4);
    if (rem > 5) BODY(5);

#undef BODY
#undef PRIME
#undef STORE_RING
#undef ADDH
#undef SSIMPAIR
#undef ROWH

    // Per-pair validity (OWD even -> pairs are all-or-nothing valid).
    float acc = 0.f;
    if (ocol + 1 < OWD) acc += accA;   // cols ocol, ocol+1
    if (ocol + 3 < OWD) acc += accB;   // cols ocol+2, ocol+3

    #pragma unroll
    for (int off = 16; off; off >>= 1)
        acc += __shfl_xor_sync(0xffffffffu, acc, off);

    const int lane = tid & 31;
    const int warp = tid >> 5;
    if (lane == 0) ws[warp] = acc;
    __syncthreads();
    if (tid == 0) {
        float b = ws[0] + ws[1] + ws[2] + ws[3];
        atomicAdd(&g_sum, (double)b);
        __threadfence();
        unsigned n = atomicAdd(&g_cnt, 1u);
        if (n == NBLK - 1) {
            double s = atomicAdd(&g_sum, 0.0);  // coherent read of final sum
            out[0] = (float)(s * (1.0 / ((double)OWD * (double)OHT)));
            g_sum = 0.0;      // reset for next graph replay
            g_cnt = 0u;
        }
    }
}

extern "C" void kernel_launch(void* const* d_in, const int* in_sizes, int n_in,
                              void* d_out, int out_size) {
    const float* O = (const float*)d_in[0];
    const float* T = (const float*)d_in[1];
    // Hint max shared carveout so 4 CTAs/SM (4 x 43KB) fit. Hint only; safe.
    cudaFuncSetAttribute(ssim_main,
                         cudaFuncAttributePreferredSharedMemoryCarveout, 100);
    ssim_main<<<dim3(GX, NSTR), TPB>>>(O, T, (float*)d_out);
}